// round 2
// baseline (speedup 1.0000x reference)
#include <cuda_runtime.h>
#include <math.h>

// Problem constants (shapes fixed by the dataset)
#define DV     256
#define HIDV   512
#define O_MAX  50000
#define E_MAX  200000
#define CONSTV 10.0f

// ---------------- static device scratch (no allocs allowed) ----------------
__device__ float g_W1p[256 * 1024];             // repacked W1: [256,1024]  (top|bot)
__device__ float g_W2p[1024 * 256];             // repacked W2: [1024,256]  (left;right)
__device__ float g_P[(size_t)O_MAX * 1024];     // per-node precomputed X@W1' : [O,1024]
__device__ float g_H[(size_t)O_MAX * 1024];     // accumulated  [Σ w h | Σ w h] : [O,1024]
__device__ float g_m[O_MAX];                    // per-node max(conf, CONST)
__device__ float g_Ws[O_MAX];                   // Σ w over sub-edges
__device__ float g_Wo[O_MAX];                   // Σ w over obj-edges
__device__ int   g_pairs[2 * E_MAX];            // normalized int32 pairs
__device__ int   g_is64;                        // dtype flag

// ---------------- vector reduction (no return) ----------------
__device__ __forceinline__ void red_add_v4(float* addr, float a, float b, float c, float d) {
    asm volatile("red.global.add.v4.f32 [%0], {%1,%2,%3,%4};"
                 :: "l"(addr), "f"(a), "f"(b), "f"(c), "f"(d) : "memory");
}

// ---------------- kernels ----------------

// Detect whether the pairs buffer is int64 or int32. Node ids are in
// [0, 50000), so as int64 every odd 32-bit word is 0. With int32 data the
// probability that 64 consecutive odd words are all zero is negligible.
__global__ void detect_kernel(const int* __restrict__ p) {
    if (threadIdx.x == 0 && blockIdx.x == 0) {
        int all0 = 1;
        for (int i = 1; i < 129; i += 2)
            if (p[i] != 0) { all0 = 0; break; }
        g_is64 = all0;
    }
}

// Normalize pairs to int32 in g_pairs regardless of source dtype.
__global__ void convert_pairs_kernel(const int* __restrict__ p, int n2) { // n2 = 2*E
    int i = blockIdx.x * blockDim.x + threadIdx.x;
    if (i >= n2) return;
    g_pairs[i] = g_is64 ? p[2 * i] : p[i];   // little-endian low word
}

// Repack W1 -> [256,1024] (cols 0..511 = W1[0:256,:], cols 512..1023 = W1[256:512,:])
// Repack W2 -> [1024,256] (rows 0..511 = W2[:, :256], rows 512..1023 = W2[:, 256:])
__global__ void repack_kernel(const float* __restrict__ W1, const float* __restrict__ W2) {
    int i = blockIdx.x * blockDim.x + threadIdx.x;
    if (i < 256 * 1024) {
        int k = i >> 10, j = i & 1023;
        g_W1p[i] = (j < 512) ? W1[k * 512 + j] : W1[(k + 256) * 512 + (j - 512)];
    }
    if (i < 1024 * 256) {
        int k = i >> 8, j = i & 255;
        g_W2p[i] = (k < 512) ? W2[k * 512 + j] : W2[(k - 512) * 512 + (j + 256)];
    }
}

__global__ void init_kernel(int O) {
    int n4 = O * 256;  // O*1024/4 float4s
    float4 z = make_float4(0.f, 0.f, 0.f, 0.f);
    float4* H4 = reinterpret_cast<float4*>(g_H);
    for (int i = blockIdx.x * blockDim.x + threadIdx.x; i < n4; i += gridDim.x * blockDim.x)
        H4[i] = z;
    for (int i = blockIdx.x * blockDim.x + threadIdx.x; i < O; i += gridDim.x * blockDim.x) {
        g_m[i] = CONSTV; g_Ws[i] = 0.f; g_Wo[i] = 0.f;
    }
}

// seg-max of confidence into g_m (init CONSTV; only conf > CONSTV can win, all positive
// so float-as-int atomicMax ordering is valid)
__global__ void edge_max_kernel(const float* __restrict__ conf, int E) {
    int e = blockIdx.x * blockDim.x + threadIdx.x;
    if (e >= E) return;
    float c = conf[e];
    if (c > CONSTV) {
        int s = g_pairs[2 * e], o = g_pairs[2 * e + 1];
        atomicMax((int*)&g_m[s], __float_as_int(c));
        atomicMax((int*)&g_m[o], __float_as_int(c));
    }
}

// Classic 128x128x16 fp32 SGEMM, 256 threads, 8x8 per thread.
// EPI==0: C[M,N] = A@B plain store.
// EPI==1: fused BGConv epilogue: out = (acc + Ws*b2[c] + Wo*b2[c+256] + sw*X[r,c]) / (Ws+Wo+sw)
template <int EPI>
__global__ void sgemm_kernel(const float* __restrict__ A, const float* __restrict__ Bm,
                             float* __restrict__ C, int M, int N, int K,
                             const float* __restrict__ X, const float* __restrict__ b2) {
    const int BM = 128, BN = 128, BK = 16, TM = 8, TN = 8;
    __shared__ float As[BK][BM + 4];
    __shared__ float Bs[BK][BN];
    int tid = threadIdx.x;              // 256 threads
    int tx = tid & 15, ty = tid >> 4;   // 16x16 thread grid
    int bm0 = blockIdx.y * BM, bn0 = blockIdx.x * BN;

    float acc[TM][TN];
#pragma unroll
    for (int i = 0; i < TM; i++)
#pragma unroll
        for (int j = 0; j < TN; j++) acc[i][j] = 0.f;

    for (int k0 = 0; k0 < K; k0 += BK) {
        // load A tile 128x16 (transposed into smem)
#pragma unroll
        for (int l = 0; l < 2; l++) {
            int f  = tid + l * 256;
            int ar = f >> 2;            // 0..127
            int ac = (f & 3) * 4;       // 0,4,8,12
            float4 v = make_float4(0.f, 0.f, 0.f, 0.f);
            int grow = bm0 + ar;
            if (grow < M)
                v = *reinterpret_cast<const float4*>(A + (size_t)grow * K + k0 + ac);
            As[ac + 0][ar] = v.x; As[ac + 1][ar] = v.y;
            As[ac + 2][ar] = v.z; As[ac + 3][ar] = v.w;
        }
        // load B tile 16x128
#pragma unroll
        for (int l = 0; l < 2; l++) {
            int f  = tid + l * 256;
            int br = f >> 5;            // 0..15
            int bc = (f & 31) * 4;      // 0..124
            *reinterpret_cast<float4*>(&Bs[br][bc]) =
                *reinterpret_cast<const float4*>(Bm + (size_t)(k0 + br) * N + bn0 + bc);
        }
        __syncthreads();
#pragma unroll
        for (int k = 0; k < BK; k++) {
            float a[TM], b[TN];
#pragma unroll
            for (int i = 0; i < TM; i++) a[i] = As[k][ty * TM + i];
#pragma unroll
            for (int j = 0; j < TN; j++) b[j] = Bs[k][tx * TN + j];
#pragma unroll
            for (int i = 0; i < TM; i++)
#pragma unroll
                for (int j = 0; j < TN; j++) acc[i][j] = fmaf(a[i], b[j], acc[i][j]);
        }
        __syncthreads();
    }

#pragma unroll
    for (int i = 0; i < TM; i++) {
        int row = bm0 + ty * TM + i;
        if (row >= M) continue;
        if (EPI == 0) {
#pragma unroll
            for (int j = 0; j < TN; j++) {
                int col = bn0 + tx * TN + j;
                C[(size_t)row * N + col] = acc[i][j];
            }
        } else {
            float ws = g_Ws[row], wo = g_Wo[row];
            float sw = expf(CONSTV - g_m[row]);
            float inv = 1.f / (ws + wo + sw);
#pragma unroll
            for (int j = 0; j < TN; j++) {
                int col = bn0 + tx * TN + j;
                float val = acc[i][j] + ws * b2[col] + wo * b2[col + DV]
                            + sw * X[(size_t)row * DV + col];
                C[(size_t)row * N + col] = val * inv;
            }
        }
    }
}

// One warp per edge: h = relu(P[s,0:512] + P[o,512:1024] + b1);
// H[s,0:512]   += ws*h   (ws = exp(conf - m[s]))
// H[o,512:1024]+= wo*h   (wo = exp(conf - m[o]))
__global__ void edge_kernel(const float* __restrict__ conf,
                            const float* __restrict__ b1, int E) {
    int gw   = (blockIdx.x * blockDim.x + threadIdx.x) >> 5;
    int lane = threadIdx.x & 31;
    if (gw >= E) return;
    int s = g_pairs[2 * gw];
    int o = g_pairs[2 * gw + 1];
    float c  = conf[gw];
    float ws = expf(c - g_m[s]);
    float wo = expf(c - g_m[o]);
    if (lane == 0) {
        atomicAdd(&g_Ws[s], ws);
        atomicAdd(&g_Wo[o], wo);
    }
    const float4* Ps = reinterpret_cast<const float4*>(g_P + (size_t)s * 1024);
    const float4* Po = reinterpret_cast<const float4*>(g_P + (size_t)o * 1024 + 512);
    float* Hs = g_H + (size_t)s * 1024;
    float* Ho = g_H + (size_t)o * 1024 + 512;
    const float4* B1 = reinterpret_cast<const float4*>(b1);
#pragma unroll
    for (int i = 0; i < 4; i++) {
        int idx = lane + i * 32;          // 0..127 float4s = 512 floats
        float4 p = Ps[idx];
        float4 q = Po[idx];
        float4 bb = B1[idx];
        float hx = fmaxf(p.x + q.x + bb.x, 0.f);
        float hy = fmaxf(p.y + q.y + bb.y, 0.f);
        float hz = fmaxf(p.z + q.z + bb.z, 0.f);
        float hw = fmaxf(p.w + q.w + bb.w, 0.f);
        red_add_v4(Hs + idx * 4, ws * hx, ws * hy, ws * hz, ws * hw);
        red_add_v4(Ho + idx * 4, wo * hx, wo * hy, wo * hz, wo * hw);
    }
}

// ---------------- launch ----------------
extern "C" void kernel_launch(void* const* d_in, const int* in_sizes, int n_in,
                              void* d_out, int out_size) {
    const float* X     = (const float*)d_in[0];      // [O, 256]
    const int*   pairs = (const int*)d_in[1];        // [E, 2] int32 or int64 (detected)
    const float* conf  = (const float*)d_in[2];      // [E]
    const float* W1    = (const float*)d_in[3];      // [512, 512]
    const float* b1    = (const float*)d_in[4];      // [512]
    const float* W2    = (const float*)d_in[5];      // [512, 512]
    const float* b2    = (const float*)d_in[6];      // [512]
    float*       out   = (float*)d_out;              // [O, 256]

    int O = in_sizes[0] / DV;
    int E = in_sizes[2];

    detect_kernel<<<1, 32>>>(pairs);
    convert_pairs_kernel<<<(2 * E + 255) / 256, 256>>>(pairs, 2 * E);
    repack_kernel<<<1024, 256>>>(W1, W2);
    init_kernel<<<2048, 256>>>(O);
    edge_max_kernel<<<(E + 255) / 256, 256>>>(conf, E);

    // P[O,1024] = X[O,256] @ W1p[256,1024]
    {
        dim3 grid(1024 / 128, (O + 127) / 128);
        sgemm_kernel<0><<<grid, 256>>>(X, g_W1p, g_P, O, 1024, 256, nullptr, nullptr);
    }

    edge_kernel<<<(E + 7) / 8, 256>>>(conf, b1, E);

    // out[O,256] = (H[O,1024] @ W2p[1024,256] + bias/self terms) / denom
    {
        dim3 grid(256 / 128, (O + 127) / 128);
        sgemm_kernel<1><<<grid, 256>>>(g_H, g_W2p, out, O, 256, 1024, X, b2);
    }
}